// round 10
// baseline (speedup 1.0000x reference)
#include <cuda_runtime.h>
#include <math.h>

// CurveGraphic2d: 16 cubic Beziers -> 16 x 256x256 canvases.
// canvas = clip(1 - (min_d/w + eps)^aa, 0, 1); w <= 8 so min_d >= w gives
// exactly 0. Setup kernel computes samples + per-tile cull flags; main kernel
// gives each block 4 tiles (strided): dead tiles are zero-filled with STG.128,
// active tiles are rendered (culled strips write exact zeros). Disjoint
// writes -> every pixel written exactly once, no ordering hazards.

#define CANVAS_H 256
#define CANVAS_W 256
#define NSAMP 32
#define MAX_LEN 300.0f
#define EPS 1e-6f

__device__ float2        g_samples[16][NSAMP];   // (y, x) per sample
__device__ unsigned char g_skip[4096];           // [b*256 + tile] 1 = all-zero tile

// ---------------- Kernel 1: samples + tile cull flags (grid=16) -------------
__global__ __launch_bounds__(256)
void curve_setup_kernel(const float* __restrict__ inputs,   // [16,4,2]
                        const float* __restrict__ widths)   // [16]
{
    __shared__ float4 ssamp[NSAMP / 2];

    const int b   = blockIdx.x;
    const int tid = threadIdx.x;

    if (tid < 32) {
        const int s = tid;
        float cy[4], cx[4];
#pragma unroll
        for (int i = 0; i < 4; i++) {
            cy[i] = inputs[(b * 4 + i) * 2 + 0] * (float)CANVAS_H;
            cx[i] = inputs[(b * 4 + i) * 2 + 1] * (float)CANVAS_W;
        }

        const float t = (float)s / 31.0f;           // linspace(0,1,32)
        const float u = 1.0f - t;
        const float B0 = u * u * u;
        const float B1 = 3.0f * t * u * u;
        const float B2 = 3.0f * t * t * u;
        const float B3 = t * t * t;

        // Full-curve sample (arc length)
        const float py = B0 * cy[0] + B1 * cy[1] + B2 * cy[2] + B3 * cy[3];
        const float px = B0 * cx[0] + B1 * cx[1] + B2 * cx[2] + B3 * cx[3];

        const float pym = __shfl_up_sync(0xffffffffu, py, 1);
        const float pxm = __shfl_up_sync(0xffffffffu, px, 1);
        const float dyy = py - pym;
        const float dxx = px - pxm;
        float seg = (s > 0) ? sqrtf(dyy * dyy + dxx * dxx) : 0.0f;
#pragma unroll
        for (int off = 16; off; off >>= 1)
            seg += __shfl_xor_sync(0xffffffffu, seg, off);
        const float arc = seg;

        const float tt = fminf(1.0f, MAX_LEN / (arc + EPS));
        const float ut = 1.0f - tt;

        // de Casteljau left subdivision at tt
        const float b0y = ut * cy[0] + tt * cy[1], b0x = ut * cx[0] + tt * cx[1];
        const float b1y = ut * cy[1] + tt * cy[2], b1x = ut * cx[1] + tt * cx[2];
        const float b2y = ut * cy[2] + tt * cy[3], b2x = ut * cx[2] + tt * cx[3];
        const float c0y = ut * b0y + tt * b1y,     c0x = ut * b0x + tt * b1x;
        const float c1y = ut * b1y + tt * b2y,     c1x = ut * b1x + tt * b2x;
        const float d0y = ut * c0y + tt * c1y,     d0x = ut * c0x + tt * c1x;

        // Truncated-curve sample
        const float sy = B0 * cy[0] + B1 * b0y + B2 * c0y + B3 * d0y;
        const float sx = B0 * cx[0] + B1 * b0x + B2 * c0x + B3 * d0x;

        ((float2*)ssamp)[s] = make_float2(sy, sx);
        g_samples[b][s]     = make_float2(sy, sx);
    }
    __syncthreads();

    // Each thread culls one 16x16 tile of canvas b.
    const int tile = tid;
    const float tcy = (float)((tile >> 4) << 4) + 7.5f;
    const float tcx = (float)((tile & 15) << 4) + 7.5f;
    float m = 3.4e38f;
#pragma unroll
    for (int k = 0; k < NSAMP / 2; k++) {
        const float4 v = ssamp[k];
        const float dy0 = tcy - v.x;
        const float dx0 = tcx - v.y;
        m = fminf(m, fmaf(dy0, dy0, dx0 * dx0));
        const float dy1 = tcy - v.z;
        const float dx1 = tcx - v.w;
        m = fminf(m, fmaf(dy1, dy1, dx1 * dx1));
    }
    // Tile half-diagonal 8*sqrt(2)=11.3137 + 1 px fp-safety margin.
    const float thr = widths[b] + 11.3137085f + 1.0f;
    g_skip[(b << 8) | tile] = (m >= thr * thr) ? 1 : 0;
}

// ---------------- Kernel 2: zero-or-render, 4 tiles/block (grid=1024) -------
__global__ __launch_bounds__(256)
void curve_main_kernel(const float* __restrict__ widths,  // [16]
                       const float* __restrict__ aafac,   // [16]
                       float* __restrict__ out)           // [16,256,256]
{
    const int tid = threadIdx.x;

    // Preload the 4 (block-uniform) skip flags with overlapped LDGs.
    unsigned char fl[4];
#pragma unroll
    for (int j = 0; j < 4; j++)
        fl[j] = __ldg(&g_skip[j * 1024 + blockIdx.x]);

#pragma unroll
    for (int j = 0; j < 4; j++) {
        const int gt   = j * 1024 + blockIdx.x;   // global tile id
        const int b    = gt >> 8;                 // curve / canvas
        const int tile = gt & 255;
        const int ty0  = (tile >> 4) << 4;
        const int tx0  = (tile & 15) << 4;
        float* const tbase = out + (b << 16) + (ty0 << 8) + tx0;

        if (fl[j]) {
            // Dead tile: 64 threads zero it with STG.128 (4 rows x 4 float4).
            if (tid < 64) {
                const int r = tid >> 2;           // row 0..15
                const int c = (tid & 3) << 2;     // col 0,4,8,12
                *(float4*)(tbase + (r << 8) + c) = make_float4(0.f, 0.f, 0.f, 0.f);
            }
            continue;                             // block-uniform
        }

        const int lx = tid & 15;
        const int ly = tid >> 4;
        float* const optr = tbase + (ly << 8) + lx;
        const float w = __ldg(&widths[b]);

        // Warp cull: each warp covers a 2x16 strip; culled strips are exact 0.
        {
            const int lane = tid & 31;
            const float2 sp = __ldg(&g_samples[b][lane]);
            const float wcy = (float)(ty0 + (ly & ~1)) + 0.5f;
            const float wcx = (float)tx0 + 7.5f;
            const float ddy = wcy - sp.x;
            const float ddx = wcx - sp.y;
            float d2 = ddy * ddy + ddx * ddx;
#pragma unroll
            for (int off = 16; off; off >>= 1)
                d2 = fminf(d2, __shfl_xor_sync(0xffffffffu, d2, off));
            // Strip half-diagonal sqrt(7.5^2+0.5^2)=7.5166 + 0.5 margin.
            const float thr = w + 7.517f + 0.5f;
            if (d2 >= thr * thr) { *optr = 0.0f; continue; }   // warp-uniform
        }

        // Full evaluation: min squared distance over 32 samples.
        const float4* __restrict__ gs = (const float4*)g_samples[b];
        const float fy = (float)(ty0 + ly);
        const float fx = (float)(tx0 + lx);
        float m = 3.4e38f;
#pragma unroll
        for (int k = 0; k < NSAMP / 2; k++) {
            const float4 v = __ldg(&gs[k]);       // uniform LDG.128 broadcast
            const float dy0 = fy - v.x;
            const float dx0 = fx - v.y;
            m = fminf(m, fmaf(dy0, dy0, dx0 * dx0));
            const float dy1 = fy - v.z;
            const float dx1 = fx - v.w;
            m = fminf(m, fmaf(dy1, dy1, dx1 * dx1));
        }

        const float md   = sqrtf(m);
        const float base = md / w + EPS;
        const float val  = 1.0f - __powf(base, __ldg(&aafac[b]));
        *optr = fminf(fmaxf(val, 0.0f), 1.0f);
    }
}

extern "C" void kernel_launch(void* const* d_in, const int* in_sizes, int n_in,
                              void* d_out, int out_size)
{
    const float* inputs = (const float*)d_in[0];   // [16,4,2]
    const float* widths = (const float*)d_in[1];   // [16]
    const float* aafac  = (const float*)d_in[2];   // [16]
    float* out = (float*)d_out;                    // [16,256,256]

    curve_setup_kernel<<<16, 256>>>(inputs, widths);
    curve_main_kernel<<<1024, 256>>>(widths, aafac, out);
}

// round 11
// speedup vs baseline: 2.2214x; 2.2214x over previous
#include <cuda_runtime.h>
#include <math.h>

// CurveGraphic2d: 16 cubic Beziers -> 16 x 256x256 canvases.
// canvas = clip(1 - (min_d/w + eps)^aa, 0, 1); w <= 8 so min_d >= w gives
// exactly 0 -> warp-level strip culling is exact.
//
// SINGLE kernel (multi-kernel graphs cost ~3-10us of replay overhead here).
// 1024 blocks x 256 threads; block = one curve x one 16x64 pixel region.
// Warp = 2x64 strip; 4 consecutive px/thread -> one STG.128 per thread
// (dead or alive), minimizing store-issue slots and block churn.

#define CANVAS_H 256
#define CANVAS_W 256
#define NSAMP 32
#define MAX_LEN 300.0f
#define EPS 1e-6f

__global__ __launch_bounds__(256)
void curve_graphic_kernel(const float* __restrict__ inputs,   // [16,4,2]
                          const float* __restrict__ widths,   // [16]
                          const float* __restrict__ aafac,    // [16]
                          float* __restrict__ out)            // [16,256,256]
{
    __shared__ float4 ssamp[NSAMP / 2];   // 32 samples as (y,x) pairs

    const int tid = threadIdx.x;
    const int b   = blockIdx.x >> 6;      // curve / canvas
    const int reg = blockIdx.x & 63;      // region: 16 rows x 64 cols
    const int ry0 = (reg >> 2) << 4;
    const int rx0 = (reg & 3) << 6;

    const float w = widths[b];

    // ---- Prelude: warp 0 computes the 32 sample points (validated math) ----
    if (tid < 32) {
        const int s = tid;
        float cy[4], cx[4];
#pragma unroll
        for (int i = 0; i < 4; i++) {
            cy[i] = inputs[(b * 4 + i) * 2 + 0] * (float)CANVAS_H;
            cx[i] = inputs[(b * 4 + i) * 2 + 1] * (float)CANVAS_W;
        }

        const float t = (float)s / 31.0f;            // linspace(0,1,32)
        const float u = 1.0f - t;
        const float B0 = u * u * u;
        const float B1 = 3.0f * t * u * u;
        const float B2 = 3.0f * t * t * u;
        const float B3 = t * t * t;

        // Full-curve sample (arc length)
        const float py = B0 * cy[0] + B1 * cy[1] + B2 * cy[2] + B3 * cy[3];
        const float px = B0 * cx[0] + B1 * cx[1] + B2 * cx[2] + B3 * cx[3];

        const float pym = __shfl_up_sync(0xffffffffu, py, 1);
        const float pxm = __shfl_up_sync(0xffffffffu, px, 1);
        const float dyy = py - pym;
        const float dxx = px - pxm;
        float seg = (s > 0) ? sqrtf(dyy * dyy + dxx * dxx) : 0.0f;
#pragma unroll
        for (int off = 16; off; off >>= 1)
            seg += __shfl_xor_sync(0xffffffffu, seg, off);
        const float arc = seg;

        const float tt = fminf(1.0f, MAX_LEN / (arc + EPS));
        const float ut = 1.0f - tt;

        // de Casteljau left subdivision at tt
        const float b0y = ut * cy[0] + tt * cy[1], b0x = ut * cx[0] + tt * cx[1];
        const float b1y = ut * cy[1] + tt * cy[2], b1x = ut * cx[1] + tt * cx[2];
        const float b2y = ut * cy[2] + tt * cy[3], b2x = ut * cx[2] + tt * cx[3];
        const float c0y = ut * b0y + tt * b1y,     c0x = ut * b0x + tt * b1x;
        const float c1y = ut * b1y + tt * b2y,     c1x = ut * b1x + tt * b2x;
        const float d0y = ut * c0y + tt * c1y,     d0x = ut * c0x + tt * c1x;

        // Truncated-curve sample
        const float sy = B0 * cy[0] + B1 * b0y + B2 * c0y + B3 * d0y;
        const float sx = B0 * cx[0] + B1 * b0x + B2 * c0x + B3 * d0x;

        ((float2*)ssamp)[s] = make_float2(sy, sx);
    }
    __syncthreads();

    // ---- Thread geometry: warp = 2x64 strip, 4 px per thread ----
    const int wid  = tid >> 5;
    const int lane = tid & 31;
    const int row  = ry0 + (wid << 1) + (lane >> 4);
    const int x0   = rx0 + ((lane & 15) << 2);
    float4* const optr = (float4*)(out + (b << 16) + (row << 8) + x0);

    // ---- Warp cull: min distance from strip center to samples ----
    {
        const float2 sp = ((const float2*)ssamp)[lane];  // sample 'lane'
        const float scy = (float)(ry0 + (wid << 1)) + 0.5f;
        const float scx = (float)rx0 + 31.5f;
        const float ddy = scy - sp.x;
        const float ddx = scx - sp.y;
        float d2 = ddy * ddy + ddx * ddx;
#pragma unroll
        for (int off = 16; off; off >>= 1)
            d2 = fminf(d2, __shfl_xor_sync(0xffffffffu, d2, off));
        // Strip half-diagonal sqrt(0.5^2 + 31.5^2) = 31.504 + 1 px margin.
        const float thr = w + 31.504f + 1.0f;
        if (d2 >= thr * thr) {                    // warp-uniform
            *optr = make_float4(0.f, 0.f, 0.f, 0.f);
            return;
        }
    }

    // ---- Full evaluation: 4 pixels, min squared distance over 32 samples ----
    const float fy = (float)row;
    const float fx = (float)x0;
    float m0 = 3.4e38f, m1 = 3.4e38f, m2 = 3.4e38f, m3 = 3.4e38f;
#pragma unroll
    for (int k = 0; k < NSAMP / 2; k++) {
        const float4 v = ssamp[k];                // LDS.128 broadcast, 2 samples
        {
            const float dy  = fy - v.x;
            const float dy2 = dy * dy;
            const float dxa = fx - v.y;
            m0 = fminf(m0, fmaf(dxa,        dxa,        dy2));
            m1 = fminf(m1, fmaf(dxa + 1.f,  dxa + 1.f,  dy2));
            m2 = fminf(m2, fmaf(dxa + 2.f,  dxa + 2.f,  dy2));
            m3 = fminf(m3, fmaf(dxa + 3.f,  dxa + 3.f,  dy2));
        }
        {
            const float dy  = fy - v.z;
            const float dy2 = dy * dy;
            const float dxa = fx - v.w;
            m0 = fminf(m0, fmaf(dxa,        dxa,        dy2));
            m1 = fminf(m1, fmaf(dxa + 1.f,  dxa + 1.f,  dy2));
            m2 = fminf(m2, fmaf(dxa + 2.f,  dxa + 2.f,  dy2));
            m3 = fminf(m3, fmaf(dxa + 3.f,  dxa + 3.f,  dy2));
        }
    }

    const float aa   = aafac[b];
    const float rinw = 1.0f / w;
    float4 r;
    r.x = fminf(fmaxf(1.0f - __powf(sqrtf(m0) * rinw + EPS, aa), 0.0f), 1.0f);
    r.y = fminf(fmaxf(1.0f - __powf(sqrtf(m1) * rinw + EPS, aa), 0.0f), 1.0f);
    r.z = fminf(fmaxf(1.0f - __powf(sqrtf(m2) * rinw + EPS, aa), 0.0f), 1.0f);
    r.w = fminf(fmaxf(1.0f - __powf(sqrtf(m3) * rinw + EPS, aa), 0.0f), 1.0f);
    *optr = r;
}

extern "C" void kernel_launch(void* const* d_in, const int* in_sizes, int n_in,
                              void* d_out, int out_size)
{
    const float* inputs = (const float*)d_in[0];   // [16,4,2]
    const float* widths = (const float*)d_in[1];   // [16]
    const float* aafac  = (const float*)d_in[2];   // [16]
    float* out = (float*)d_out;                    // [16,256,256]

    curve_graphic_kernel<<<1024, 256>>>(inputs, widths, aafac, out);
}